// round 17
// baseline (speedup 1.0000x reference)
#include <cuda_runtime.h>
#include <cuda_bf16.h>
#include <cstdint>

#define S_LEN 2048
#define B_SZ  16
#define H_DIM 1024
#define VPS   8                        // s-rows per score block
#define BLKS_PER_COL (S_LEN / VPS)     // 256

// 8 chunk-partial slabs (race-free -> no init kernel)
__device__ float g_part[8][B_SZ * H_DIM];
__device__ float g_scoresT[B_SZ * S_LEN];   // transposed scores [b][s]
__device__ int   g_cnt[B_SZ * 64];          // per-column counters, 256B apart

// ---- scoped atomic / L2-direct load helpers (NO fences -> no L1 flush) ----
__device__ __forceinline__ int atom_add_acqrel(int* p, int v) {
    int old;
    asm volatile("atom.acq_rel.gpu.global.add.s32 %0, [%1], %2;"
                 : "=r"(old) : "l"(p), "r"(v) : "memory");
    return old;
}
__device__ __forceinline__ float4 ldcg4(const float4* p) {
    float4 v;
    asm volatile("ld.global.cg.v4.f32 {%0,%1,%2,%3}, [%4];"
                 : "=f"(v.x), "=f"(v.y), "=f"(v.z), "=f"(v.w) : "l"(p));
    return v;
}

// ---------------------------------------------------------------------------
// Kernel 1 (R8-proven, 6.27us): energy partials. j in 8 chunks of 128 floats.
// Block = 128 thr (4 warps) covers (8 h-rows) x (one chunk); warp owns
// 2 rows x 16 b = 32 accumulators, each LDS.128 feeds 8 FFMAs. grid=1024.
// ---------------------------------------------------------------------------
__global__ void __launch_bounds__(128)
energy_kernel(const float* __restrict__ lds,
              const float* __restrict__ W)
{
    __shared__ float4 s_st[16 * 32];     // [b][32 float4] (8KB)

    const int t    = threadIdx.x;
    const int warp = t >> 5;
    const int lane = t & 31;
    const int rg   = blockIdx.x >> 3;
    const int ch   = blockIdx.x & 7;
    const int row0 = rg * 8 + warp * 2;

    const float4* st4 = reinterpret_cast<const float4*>(lds);  // [B][256]
    const float4* W4  = reinterpret_cast<const float4*>(W);    // [H][256]

    const float4 w0 = W4[(size_t)row0 * 256 + ch * 32 + lane];
    const float4 w1 = W4[(size_t)(row0 + 1) * 256 + ch * 32 + lane];

    #pragma unroll
    for (int i = 0; i < 4; ++i) {
        const int v = t + i * 128;
        const int b = v >> 5;
        const int k = v & 31;
        s_st[v] = st4[b * 256 + ch * 32 + k];
    }
    __syncthreads();

    float a[32];                          // a[r*16+b]
    #pragma unroll
    for (int b = 0; b < 16; ++b) {
        const float4 s = s_st[b * 32 + lane];
        a[b]      = w0.x * s.x + w0.y * s.y + w0.z * s.z + w0.w * s.w;
        a[16 + b] = w1.x * s.x + w1.y * s.y + w1.z * s.z + w1.w * s.w;
    }

    // Value-halving butterfly: lane l ends holding warp-total of a[l].
    int n = 32;
    #pragma unroll
    for (int s = 16; s >= 1; s >>= 1) {
        const int  half = n >> 1;
        const bool up   = (lane & s) != 0;
        #pragma unroll
        for (int i = 0; i < half; ++i) {
            const float send = up ? a[i] : a[i + half];
            const float keep = up ? a[i + half] : a[i];
            a[i] = keep + __shfl_xor_sync(0xFFFFFFFF, send, s);
        }
        n = half;
    }

    const int r = lane >> 4;
    const int b = lane & 15;
    g_part[ch][(size_t)b * H_DIM + row0 + r] = a[0];
}

// ---------------------------------------------------------------------------
// Kernel 2: score + fence-free tail-fused softmax.
// Body identical to the proven R12 score. Tail: t0 stores the block's 8 sums
// (2x STG.128) and does ONE acq_rel atomic on a 256B-strided counter — no
// __threadfence, no CCTL.IVALL. The block seeing old==255 runs column b's
// softmax with ld.global.cg (L2-direct). Counter self-resets for replay.
// ---------------------------------------------------------------------------
__global__ void __launch_bounds__(128)
score_kernel(const float* __restrict__ enc,
             const float* __restrict__ bias,
             float* __restrict__ out)
{
    const int b  = blockIdx.x & (B_SZ - 1);
    const int s0 = (blockIdx.x >> 4) * VPS;
    const int t  = threadIdx.x;
    const int warp = t >> 5;
    const int lane = t & 31;

    __shared__ float red[4][VPS];
    __shared__ __align__(16) float sums[VPS];
    __shared__ int s_elect;
    if (t == 0) s_elect = 0;

    const float4* e4 = reinterpret_cast<const float4*>(enc);
    const float4* b4 = reinterpret_cast<const float4*>(bias);

    float4 g0 = b4[t];
    float4 g1 = b4[128 + t];
    #pragma unroll
    for (int c = 0; c < 8; ++c) {
        const float4* p4 = reinterpret_cast<const float4*>(g_part[c]);
        const float4 p0 = p4[b * (H_DIM / 4) + t];
        const float4 p1 = p4[b * (H_DIM / 4) + 128 + t];
        g0.x += p0.x; g0.y += p0.y; g0.z += p0.z; g0.w += p0.w;
        g1.x += p1.x; g1.y += p1.y; g1.z += p1.z; g1.w += p1.w;
    }

    float acc[VPS];
    #pragma unroll
    for (int i = 0; i < VPS; ++i) {
        const size_t row = ((size_t)(s0 + i) * B_SZ + b) * (H_DIM / 4);
        const float4 a0 = e4[row + t];
        const float4 a1 = e4[row + 128 + t];
        acc[i] = a0.x * g0.x + a0.y * g0.y + a0.z * g0.z + a0.w * g0.w
               + a1.x * g1.x + a1.y * g1.y + a1.z * g1.z + a1.w * g1.w;
    }

    #pragma unroll
    for (int i = 0; i < VPS; ++i)
        #pragma unroll
        for (int off = 16; off > 0; off >>= 1)
            acc[i] += __shfl_xor_sync(0xFFFFFFFF, acc[i], off);

    if (lane == 0) {
        #pragma unroll
        for (int i = 0; i < VPS; ++i)
            red[warp][i] = acc[i];
    }
    __syncthreads();
    if (t < VPS)
        sums[t] = red[0][t] + red[1][t] + red[2][t] + red[3][t];
    __syncthreads();

    if (t == 0) {
        const float4* s4 = reinterpret_cast<const float4*>(sums);
        float4* dst = reinterpret_cast<float4*>(g_scoresT + (size_t)b * S_LEN + s0);
        dst[0] = s4[0];
        dst[1] = s4[1];
        // acq_rel atomic: orders t0's two STG.128 above (release) and the
        // elected block's subsequent reads (acquire). No fence, no L1 flush.
        const int old = atom_add_acqrel(&g_cnt[b * 64], 1);
        if (old == BLKS_PER_COL - 1) s_elect = 1;
    }
    __syncthreads();
    if (!s_elect) return;

    // ====== Elected (last) block for column b: softmax, L2-direct. ======
    const float4* c4 = reinterpret_cast<const float4*>(g_scoresT + (size_t)b * S_LEN);
    __shared__ float sm4[4];

    float4 v[4];
    #pragma unroll
    for (int i = 0; i < 4; ++i)
        v[i] = ldcg4(c4 + t + i * 128);

    // Pass 1: max
    float mx = -3.402823466e38f;
    #pragma unroll
    for (int i = 0; i < 4; ++i)
        mx = fmaxf(mx, fmaxf(fmaxf(v[i].x, v[i].y), fmaxf(v[i].z, v[i].w)));
    #pragma unroll
    for (int off = 16; off > 0; off >>= 1)
        mx = fmaxf(mx, __shfl_xor_sync(0xFFFFFFFF, mx, off));
    if (lane == 0) sm4[warp] = mx;
    __syncthreads();
    mx = fmaxf(fmaxf(sm4[0], sm4[1]), fmaxf(sm4[2], sm4[3]));
    __syncthreads();

    // Pass 2: exp + sum (keep exps in registers)
    float sum = 0.f;
    #pragma unroll
    for (int i = 0; i < 4; ++i) {
        v[i].x = __expf(v[i].x - mx); v[i].y = __expf(v[i].y - mx);
        v[i].z = __expf(v[i].z - mx); v[i].w = __expf(v[i].w - mx);
        sum += v[i].x + v[i].y + v[i].z + v[i].w;
    }
    #pragma unroll
    for (int off = 16; off > 0; off >>= 1)
        sum += __shfl_xor_sync(0xFFFFFFFF, sum, off);
    if (lane == 0) sm4[warp] = sum;
    __syncthreads();
    const float inv = 1.0f / (sm4[0] + sm4[1] + sm4[2] + sm4[3]);

    // Pass 3: scale + scatter-store to out[s][b]
    #pragma unroll
    for (int i = 0; i < 4; ++i) {
        const int s = (t + i * 128) * 4;
        out[(size_t)(s + 0) * B_SZ + b] = v[i].x * inv;
        out[(size_t)(s + 1) * B_SZ + b] = v[i].y * inv;
        out[(size_t)(s + 2) * B_SZ + b] = v[i].z * inv;
        out[(size_t)(s + 3) * B_SZ + b] = v[i].w * inv;
    }

    // Re-arm counter for the next graph replay.
    if (t == 0) g_cnt[b * 64] = 0;
}

// ---------------------------------------------------------------------------
extern "C" void kernel_launch(void* const* d_in, const int* in_sizes, int n_in,
                              void* d_out, int out_size)
{
    const float* enc  = (const float*)d_in[0];  // [S,B,H]
    const float* lds  = (const float*)d_in[1];  // [2,1,B,H]
    const float* W    = (const float*)d_in[2];  // [H,H]
    const float* bias = (const float*)d_in[3];  // [H]
    float* out = (float*)d_out;                 // [1,1,S,B] == [S,B]

    energy_kernel<<<1024, 128>>>(lds, W);
    score_kernel<<<(S_LEN / VPS) * B_SZ, 128>>>(enc, bias, out);
}